// round 14
// baseline (speedup 1.0000x reference)
#include <cuda_runtime.h>
#include <math.h>
#include <float.h>

#define Bq 64
#define Nq 16384
#define Mq 64
#define Cq 256
#define GAMMAq 0.95f
#define EPSq 1e-16f
#define NOUT 66    // M + 2
#define CHUNKS 64  // K2 grid.x = Nq/256

// ---------------- scratch (static device globals; no allocation) ----------------
__device__ float g_k[Bq * Mq];
__device__ float g_beta[Bq];
__device__ float g_gate[Bq];
__device__ float g_E[(size_t)Bq * Nq];           // exp(beta*(sim-1))
__device__ float g_psum[Bq * CHUNKS];            // per-K2-block partial sums of E
__device__ unsigned long long g_cand[Bq * 16];   // 4 chunks x 4 candidate keys
__device__ int g_ticket[Bq];                     // last-block-done tickets

// ---------------- kernel 1: projection, warp per (batch, output) ----------------
__global__ void ntm_proj_kernel(const float* __restrict__ emb,
                                const float* __restrict__ W,
                                const float* __restrict__ bias) {
    if (blockIdx.x == 0 && threadIdx.x < Bq) g_ticket[threadIdx.x] = 0;

    const int wglob = (blockIdx.x * blockDim.x + threadIdx.x) >> 5;
    const int lane = threadIdx.x & 31;
    if (wglob < Bq * NOUT) {
        const int b = wglob / NOUT;
        const int o = wglob - b * NOUT;

        const float* __restrict__ e = emb + (size_t)b * Cq;
        const float* __restrict__ w = W + (size_t)o * Cq;

        float acc = 0.0f;
#pragma unroll
        for (int i = 0; i < 8; i++) {
            const int c = lane + 32 * i;
            acc = fmaf(__ldg(&e[c]), __ldg(&w[c]), acc);
        }
#pragma unroll
        for (int s = 16; s > 0; s >>= 1)
            acc += __shfl_xor_sync(0xffffffffu, acc, s);

        if (lane == 0) {
            acc += bias[o];
            if (o < Mq) {
                g_k[b * Mq + o] = acc;
            } else if (o == Mq) {
                g_beta[b] = (acc > 20.0f) ? acc : log1pf(expf(acc));
            } else {
                g_gate[b] = 1.0f / (1.0f + expf(-acc));
            }
        }
    }
    cudaTriggerProgrammaticLaunchCompletion();
}

// ---------------- kernel 2: fused sim/exp + new_memory streaming pass -----------
// grid: (CHUNKS, Bq), block 512. 256-row chunks, 8-deep load/store bursts.
// No min-blocks pin: ptxas free to hold m[8] in regs without spilling.
__global__ void __launch_bounds__(512)
ntm_stream_kernel(const float* __restrict__ memory,
                  const float* __restrict__ w_prev,
                  float* __restrict__ out) {
    const int b = blockIdx.y;
    const int n0 = blockIdx.x * 256;
    const int tid = threadIdx.x;
    const int hw = tid >> 4;
    const int l16 = tid & 15;

    __shared__ float4 sh_k4[16];
    __shared__ float sh_wr[256];
    __shared__ float sh_wlu[256];
    __shared__ float sh_E[256];
    __shared__ float s_knorm;

    const float4* __restrict__ mem4 = (const float4*)memory;
    const size_t base = ((size_t)b * Nq + n0 + hw) * (Mq / 4) + l16;

    // ---- pre-sync: Phase A loads + w_prev staging (pure inputs) ----
    float4 m[8];
#pragma unroll
    for (int r = 0; r < 8; r++)
        m[r] = __ldcs(&mem4[base + (size_t)r * 32 * (Mq / 4)]);

    if (tid < 256) {
        const int n = n0 + tid;
        sh_wr[tid]  = w_prev[((size_t)b * 3 + 1) * Nq + n];
        sh_wlu[tid] = w_prev[((size_t)b * 3 + 2) * Nq + n];
    }

    // ---- wait for proj outputs ----
    cudaGridDependencySynchronize();

    const float gv = g_gate[b];
    const float beta = g_beta[b];

    float kn = 0.0f;
    if (tid < 16) {
        const float4 k4 = ((const float4*)(g_k + (size_t)b * Mq))[tid];
        sh_k4[tid] = k4;
        kn = k4.x * k4.x + k4.y * k4.y + k4.z * k4.z + k4.w * k4.w;
    }
    if (tid < 32) {
#pragma unroll
        for (int s = 8; s > 0; s >>= 1)
            kn += __shfl_xor_sync(0xffffffffu, kn, s);
        if (tid == 0) s_knorm = sqrtf(kn);
    }
    __syncthreads();

    const float knorm = s_knorm;
    const float4 kv = sh_k4[l16];
    float* __restrict__ newmem = out + (size_t)Bq * 3 * Nq;
    float4* __restrict__ out4 = (float4*)newmem;

    // Phase B: all 8 stores (long write burst, independent of shuffle chains)
#pragma unroll
    for (int r = 0; r < 8; r++) {
        const int local = hw + 32 * r;
        const float ww = gv * sh_wr[local] + (1.0f - gv) * sh_wlu[local];
        float4 o4;
        o4.x = m[r].x + ww * kv.x;
        o4.y = m[r].y + ww * kv.y;
        o4.z = m[r].z + ww * kv.z;
        o4.w = m[r].w + ww * kv.w;
        __stcs(&out4[base + (size_t)r * 32 * (Mq / 4)], o4);
    }

    // Phase C: reductions -> E = exp(beta*(sim-1))
#pragma unroll
    for (int r = 0; r < 8; r++) {
        float dot = m[r].x * kv.x + m[r].y * kv.y + m[r].z * kv.z + m[r].w * kv.w;
        float nrm = m[r].x * m[r].x + m[r].y * m[r].y + m[r].z * m[r].z + m[r].w * m[r].w;
#pragma unroll
        for (int s = 8; s > 0; s >>= 1) {
            dot += __shfl_xor_sync(0xffffffffu, dot, s);
            nrm += __shfl_xor_sync(0xffffffffu, nrm, s);
        }
        if (l16 == 0) {
            const float sim = dot / (knorm * sqrtf(nrm) + EPSq);
            sh_E[hw + 32 * r] = expf(beta * (sim - 1.0f));
        }
    }
    __syncthreads();

    if (tid < 64) {
        const float4 e4 = ((const float4*)sh_E)[tid];
        ((float4*)(g_E + (size_t)b * Nq + n0))[tid] = e4;
        float ps = e4.x + e4.y + e4.z + e4.w;
#pragma unroll
        for (int s = 16; s > 0; s >>= 1)
            ps += __shfl_xor_sync(0xffffffffu, ps, s);
        // lanes 0 of the two participating warps: combine via shared? simpler:
        // warp-level sum covered tid 0..31 and 32..63 separately; store two partials
        if ((tid & 31) == 0) g_psum[b * CHUNKS + blockIdx.x] = 0.0f;  // placeholder init
    }
    __syncthreads();
    if (tid < 64) {
        const float4 e4 = ((const float4*)sh_E)[tid];
        float ps = e4.x + e4.y + e4.z + e4.w;
#pragma unroll
        for (int s = 16; s > 0; s >>= 1)
            ps += __shfl_xor_sync(0xffffffffu, ps, s);
        if (tid == 0) {
            // add second warp's partial deterministically
            float ps2 = 0.0f;
            for (int i = 128; i < 256; i++) ps2 += sh_E[i];
            // recompute first half exactly from the warp-reduced value
            g_psum[b * CHUNKS + blockIdx.x] = ps + 0.0f * ps2;  // ps covers 0..127? no
        }
    }
    __syncthreads();
    // Deterministic, simple and cheap: thread 0 sums all 256 (256 adds, smem-resident)
    if (tid == 0) {
        float ps = 0.0f;
#pragma unroll 8
        for (int i = 0; i < 256; i++) ps += sh_E[i];
        g_psum[b * CHUNKS + blockIdx.x] = ps;
    }
    cudaTriggerProgrammaticLaunchCompletion();
}

// ---------------- kernel 3: elementwise (float4) + top-4 + last-block merge -----
// grid: 256 blocks (4 per batch), 1024 threads, 4 CONSECUTIVE elems/thread.
__global__ void __launch_bounds__(1024, 1)
ntm_elem_kernel(const float* __restrict__ w_prev, float* __restrict__ out) {
    const int blk = blockIdx.x;
    const int b = blk >> 2;
    const int c = blk & 3;
    const int tid = threadIdx.x;
    const int warp = tid >> 5;
    const int lane = tid & 31;
    const int n = c * 4096 + tid * 4;   // 4 consecutive elements per thread

    __shared__ float s_inv;
    __shared__ unsigned long long sh_keys[128];
    __shared__ int s_last;

    const float* __restrict__ wup  = w_prev + (size_t)b * 3 * Nq;
    const float* __restrict__ wrp  = wup + Nq;
    const float* __restrict__ wlup = wup + 2 * Nq;
    float* __restrict__ w_u_out  = out + (size_t)b * 3 * Nq;
    float* __restrict__ w_r_out  = w_u_out + Nq;
    float* __restrict__ w_lu_out = w_u_out + 2 * Nq;

    // ---- pre-sync: vectorized input loads + zero-fill (independent of K2) ----
    const float4 vu = *(const float4*)(wup + n);
    const float4 vr = *(const float4*)(wrp + n);
    const float4 vl = *(const float4*)(wlup + n);
    __stcs((float4*)(w_lu_out + n), make_float4(0.f, 0.f, 0.f, 0.f));

    // ---- wait for K2 (E, psum, gate all visible) ----
    cudaGridDependencySynchronize();

    // reduce the 64 partial sums (deterministic fixed order)
    if (tid < 32) {
        const float* __restrict__ ps = g_psum + b * CHUNKS;
        float v = ps[tid] + ps[tid + 32];
#pragma unroll
        for (int s = 16; s > 0; s >>= 1)
            v += __shfl_xor_sync(0xffffffffu, v, s);
        if (tid == 0) s_inv = 1.0f / v;
    }
    __syncthreads();
    const float inv = s_inv;
    const float gv = g_gate[b];

    const float4 e4 = *(const float4*)(g_E + (size_t)b * Nq + n);

    float4 wr4, wu4;
    wr4.x = e4.x * inv;  wr4.y = e4.y * inv;  wr4.z = e4.z * inv;  wr4.w = e4.w * inv;
    wu4.x = GAMMAq * vu.x + wr4.x + (gv * vr.x + (1.0f - gv) * vl.x);
    wu4.y = GAMMAq * vu.y + wr4.y + (gv * vr.y + (1.0f - gv) * vl.y);
    wu4.z = GAMMAq * vu.z + wr4.z + (gv * vr.z + (1.0f - gv) * vl.z);
    wu4.w = GAMMAq * vu.w + wr4.w + (gv * vr.w + (1.0f - gv) * vl.w);

    __stcs((float4*)(w_r_out + n), wr4);
    __stcs((float4*)(w_u_out + n), wu4);

    // thread-local top-4 over its 4 values (packed keys; wu > 0)
    unsigned long long tk[4] = {~0ULL, ~0ULL, ~0ULL, ~0ULL};
    const float wvals[4] = {wu4.x, wu4.y, wu4.z, wu4.w};
#pragma unroll
    for (int j = 0; j < 4; j++) {
        const unsigned long long key =
            ((unsigned long long)__float_as_uint(wvals[j]) << 32) | (unsigned int)(n + j);
        if (key < tk[3]) {
            tk[3] = key;
#pragma unroll
            for (int q = 3; q > 0; q--) {
                if (tk[q] < tk[q - 1]) {
                    unsigned long long t = tk[q]; tk[q] = tk[q - 1]; tk[q - 1] = t;
                }
            }
        }
    }

    // per-warp top-4 via 4 rounds of shfl argmin + pop (no barriers)
#pragma unroll
    for (int round = 0; round < 4; round++) {
        unsigned long long v = tk[0];
#pragma unroll
        for (int s = 16; s > 0; s >>= 1) {
            const unsigned long long o = __shfl_xor_sync(0xffffffffu, v, s);
            if (o < v) v = o;
        }
        if (tk[0] == v) {  // unique key -> exactly one popper
            tk[0] = tk[1]; tk[1] = tk[2]; tk[2] = tk[3]; tk[3] = ~0ULL;
        }
        if (lane == 0) sh_keys[warp * 4 + round] = v;
    }
    __syncthreads();

    // warp 0: reduce 128 candidates -> this chunk's top-4 -> g_cand
    if (warp == 0) {
        unsigned long long bk[4] = {~0ULL, ~0ULL, ~0ULL, ~0ULL};
#pragma unroll
        for (int j = 0; j < 4; j++) {
            const unsigned long long key = sh_keys[lane + 32 * j];
            if (key < bk[3]) {
                bk[3] = key;
#pragma unroll
                for (int q = 3; q > 0; q--) {
                    if (bk[q] < bk[q - 1]) {
                        unsigned long long t = bk[q]; bk[q] = bk[q - 1]; bk[q - 1] = t;
                    }
                }
            }
        }
#pragma unroll
        for (int round = 0; round < 4; round++) {
            unsigned long long v = bk[0];
#pragma unroll
            for (int s = 16; s > 0; s >>= 1) {
                const unsigned long long o = __shfl_xor_sync(0xffffffffu, v, s);
                if (o < v) v = o;
            }
            if (bk[0] == v) {
                bk[0] = bk[1]; bk[1] = bk[2]; bk[2] = bk[3]; bk[3] = ~0ULL;
            }
            if (lane == round) g_cand[(b * 4 + c) * 4 + round] = v;
        }
    }
    __syncthreads();

    // ticket: last block of this batch merges + scatters
    if (tid == 0) {
        __threadfence();
        s_last = (atomicAdd(&g_ticket[b], 1) == 3);
    }
    __syncthreads();

    if (s_last && warp == 0) {
        unsigned long long key = (lane < 16) ? g_cand[b * 16 + lane] : ~0ULL;
#pragma unroll
        for (int round = 0; round < 4; round++) {
            unsigned long long v = key;
#pragma unroll
            for (int s = 16; s > 0; s >>= 1) {
                const unsigned long long o = __shfl_xor_sync(0xffffffffu, v, s);
                if (o < v) v = o;
            }
            if (key == v) key = ~0ULL;  // pop winner
            if (lane == round)
                w_lu_out[(int)(unsigned int)(v & 0xffffffffu)] = 1.0f;
        }
    }
}

// ---------------- launch ----------------
extern "C" void kernel_launch(void* const* d_in, const int* in_sizes, int n_in,
                              void* d_out, int out_size) {
    const float* emb    = (const float*)d_in[0];  // (64, 256)
    const float* w_prev = (const float*)d_in[1];  // (64, 3, 16384)
    const float* memory = (const float*)d_in[2];  // (64, 16384, 64)
    const float* W      = (const float*)d_in[3];  // (66, 256)
    const float* bias   = (const float*)d_in[4];  // (66,)
    float* out = (float*)d_out;  // [w (64*3*16384) | new_memory (64*16384*64)]

    const int nwarps = Bq * NOUT;                 // 4224
    const int nblk1 = (nwarps * 32 + 255) / 256;  // 528
    ntm_proj_kernel<<<nblk1, 256>>>(emb, W, bias);

    // K2: PDL secondary of proj
    {
        cudaLaunchConfig_t cfg = {};
        cfg.gridDim = dim3(CHUNKS, Bq);
        cfg.blockDim = dim3(512);
        cudaLaunchAttribute attr[1];
        attr[0].id = cudaLaunchAttributeProgrammaticStreamSerialization;
        attr[0].val.programmaticStreamSerializationAllowed = 1;
        cfg.attrs = attr;
        cfg.numAttrs = 1;
        cudaLaunchKernelEx(&cfg, ntm_stream_kernel, memory, w_prev, out);
    }

    // K3: PDL secondary of K2
    {
        cudaLaunchConfig_t cfg = {};
        cfg.gridDim = dim3(Bq * 4);
        cfg.blockDim = dim3(1024);
        cudaLaunchAttribute attr[1];
        attr[0].id = cudaLaunchAttributeProgrammaticStreamSerialization;
        attr[0].val.programmaticStreamSerializationAllowed = 1;
        cfg.attrs = attr;
        cfg.numAttrs = 1;
        cudaLaunchKernelEx(&cfg, ntm_elem_kernel, w_prev, out);
    }
}

// round 15
// speedup vs baseline: 1.2555x; 1.2555x over previous
#include <cuda_runtime.h>
#include <math.h>
#include <float.h>

#define Bq 64
#define Nq 16384
#define Mq 64
#define Cq 256
#define GAMMAq 0.95f
#define EPSq 1e-16f
#define NOUT 66     // M + 2
#define CHUNKS 128  // K2 grid.x = Nq/128

// ---------------- scratch (static device globals; no allocation) ----------------
__device__ float g_k[Bq * Mq];
__device__ float g_beta[Bq];
__device__ float g_gate[Bq];
__device__ float g_E[(size_t)Bq * Nq];           // exp(beta*(sim-1))
__device__ float g_psum[Bq * CHUNKS];            // per-K2-block partial sums of E
__device__ unsigned long long g_cand[Bq * 16];   // 4 chunks x 4 candidate keys
__device__ int g_ticket[Bq];                     // last-block-done tickets

// ---------------- kernel 1: projection, warp per (batch, output) ----------------
__global__ void ntm_proj_kernel(const float* __restrict__ emb,
                                const float* __restrict__ W,
                                const float* __restrict__ bias) {
    if (blockIdx.x == 0 && threadIdx.x < Bq) g_ticket[threadIdx.x] = 0;

    const int wglob = (blockIdx.x * blockDim.x + threadIdx.x) >> 5;
    const int lane = threadIdx.x & 31;
    if (wglob < Bq * NOUT) {
        const int b = wglob / NOUT;
        const int o = wglob - b * NOUT;

        const float* __restrict__ e = emb + (size_t)b * Cq;
        const float* __restrict__ w = W + (size_t)o * Cq;

        float acc = 0.0f;
#pragma unroll
        for (int i = 0; i < 8; i++) {
            const int c = lane + 32 * i;
            acc = fmaf(__ldg(&e[c]), __ldg(&w[c]), acc);
        }
#pragma unroll
        for (int s = 16; s > 0; s >>= 1)
            acc += __shfl_xor_sync(0xffffffffu, acc, s);

        if (lane == 0) {
            acc += bias[o];
            if (o < Mq) {
                g_k[b * Mq + o] = acc;
            } else if (o == Mq) {
                g_beta[b] = (acc > 20.0f) ? acc : log1pf(expf(acc));
            } else {
                g_gate[b] = 1.0f / (1.0f + expf(-acc));
            }
        }
    }
    cudaTriggerProgrammaticLaunchCompletion();
}

// ---------------- kernel 2: fused sim/exp + new_memory streaming pass -----------
// grid: (CHUNKS, Bq), block 512, >=3 blocks/SM. Phase A/B/C structure.
__global__ void __launch_bounds__(512, 3)
ntm_stream_kernel(const float* __restrict__ memory,
                  const float* __restrict__ w_prev,
                  float* __restrict__ out) {
    const int b = blockIdx.y;
    const int n0 = blockIdx.x * 128;
    const int tid = threadIdx.x;
    const int hw = tid >> 4;
    const int l16 = tid & 15;

    __shared__ float4 sh_k4[16];
    __shared__ float sh_wr[128];
    __shared__ float sh_wlu[128];
    __shared__ float sh_E[128];
    __shared__ float s_knorm;

    const float4* __restrict__ mem4 = (const float4*)memory;
    const size_t base = ((size_t)b * Nq + n0 + hw) * (Mq / 4) + l16;

    // ---- pre-sync: Phase A loads + w_prev staging (pure inputs) ----
    float4 m[4];
#pragma unroll
    for (int r = 0; r < 4; r++)
        m[r] = __ldcs(&mem4[base + (size_t)r * 32 * (Mq / 4)]);

    if (tid < 128) {
        const int n = n0 + tid;
        sh_wr[tid]  = w_prev[((size_t)b * 3 + 1) * Nq + n];
        sh_wlu[tid] = w_prev[((size_t)b * 3 + 2) * Nq + n];
    }

    // ---- wait for proj outputs ----
    cudaGridDependencySynchronize();

    const float gv = g_gate[b];
    const float beta = g_beta[b];

    float kn = 0.0f;
    if (tid < 16) {
        const float4 k4 = ((const float4*)(g_k + (size_t)b * Mq))[tid];
        sh_k4[tid] = k4;
        kn = k4.x * k4.x + k4.y * k4.y + k4.z * k4.z + k4.w * k4.w;
    }
    if (tid < 32) {
#pragma unroll
        for (int s = 8; s > 0; s >>= 1)
            kn += __shfl_xor_sync(0xffffffffu, kn, s);
        if (tid == 0) s_knorm = sqrtf(kn);
    }
    __syncthreads();

    const float knorm = s_knorm;
    const float4 kv = sh_k4[l16];
    float* __restrict__ newmem = out + (size_t)Bq * 3 * Nq;
    float4* __restrict__ out4 = (float4*)newmem;

    // Phase B: all stores (independent of shuffle chains)
#pragma unroll
    for (int r = 0; r < 4; r++) {
        const int local = hw + 32 * r;
        const float ww = gv * sh_wr[local] + (1.0f - gv) * sh_wlu[local];
        float4 o4;
        o4.x = m[r].x + ww * kv.x;
        o4.y = m[r].y + ww * kv.y;
        o4.z = m[r].z + ww * kv.z;
        o4.w = m[r].w + ww * kv.w;
        __stcs(&out4[base + (size_t)r * 32 * (Mq / 4)], o4);
    }

    // Phase C: reductions -> E = exp(beta*(sim-1))
#pragma unroll
    for (int r = 0; r < 4; r++) {
        float dot = m[r].x * kv.x + m[r].y * kv.y + m[r].z * kv.z + m[r].w * kv.w;
        float nrm = m[r].x * m[r].x + m[r].y * m[r].y + m[r].z * m[r].z + m[r].w * m[r].w;
#pragma unroll
        for (int s = 8; s > 0; s >>= 1) {
            dot += __shfl_xor_sync(0xffffffffu, dot, s);
            nrm += __shfl_xor_sync(0xffffffffu, nrm, s);
        }
        if (l16 == 0) {
            const float sim = dot / (knorm * sqrtf(nrm) + EPSq);
            sh_E[hw + 32 * r] = expf(beta * (sim - 1.0f));
        }
    }
    __syncthreads();

    if (tid < 32) {
        const float4 e4 = ((const float4*)sh_E)[tid];
        ((float4*)(g_E + (size_t)b * Nq + n0))[tid] = e4;
        float ps = e4.x + e4.y + e4.z + e4.w;
#pragma unroll
        for (int s = 16; s > 0; s >>= 1)
            ps += __shfl_xor_sync(0xffffffffu, ps, s);
        if (tid == 0) g_psum[b * CHUNKS + blockIdx.x] = ps;
    }
    cudaTriggerProgrammaticLaunchCompletion();
}

// ---------------- kernel 3: elementwise (float4) + top-4 + last-block merge -----
// grid: 256 blocks (4 per batch), 1024 threads, 4 CONSECUTIVE elems/thread.
__global__ void __launch_bounds__(1024, 1)
ntm_elem_kernel(const float* __restrict__ w_prev, float* __restrict__ out) {
    const int blk = blockIdx.x;
    const int b = blk >> 2;
    const int c = blk & 3;
    const int tid = threadIdx.x;
    const int warp = tid >> 5;
    const int lane = tid & 31;
    const int n = c * 4096 + tid * 4;   // 4 consecutive elements per thread

    __shared__ float s_inv;
    __shared__ unsigned long long sh_keys[128];
    __shared__ int s_last;

    const float* __restrict__ wup  = w_prev + (size_t)b * 3 * Nq;
    const float* __restrict__ wrp  = wup + Nq;
    const float* __restrict__ wlup = wup + 2 * Nq;
    float* __restrict__ w_u_out  = out + (size_t)b * 3 * Nq;
    float* __restrict__ w_r_out  = w_u_out + Nq;
    float* __restrict__ w_lu_out = w_u_out + 2 * Nq;

    // ---- pre-sync: vectorized input loads + zero-fill (independent of K2) ----
    const float4 vu = *(const float4*)(wup + n);
    const float4 vr = *(const float4*)(wrp + n);
    const float4 vl = *(const float4*)(wlup + n);
    __stcs((float4*)(w_lu_out + n), make_float4(0.f, 0.f, 0.f, 0.f));

    // ---- wait for K2 (E, psum, gate all visible) ----
    cudaGridDependencySynchronize();

    // reduce the 128 partial sums (deterministic fixed order)
    if (tid < 32) {
        const float* __restrict__ ps = g_psum + b * CHUNKS;
        float v = ps[tid] + ps[tid + 32] + ps[tid + 64] + ps[tid + 96];
#pragma unroll
        for (int s = 16; s > 0; s >>= 1)
            v += __shfl_xor_sync(0xffffffffu, v, s);
        if (tid == 0) s_inv = 1.0f / v;
    }
    __syncthreads();
    const float inv = s_inv;
    const float gv = g_gate[b];

    const float4 e4 = *(const float4*)(g_E + (size_t)b * Nq + n);

    float4 wr4, wu4;
    wr4.x = e4.x * inv;  wr4.y = e4.y * inv;  wr4.z = e4.z * inv;  wr4.w = e4.w * inv;
    wu4.x = GAMMAq * vu.x + wr4.x + (gv * vr.x + (1.0f - gv) * vl.x);
    wu4.y = GAMMAq * vu.y + wr4.y + (gv * vr.y + (1.0f - gv) * vl.y);
    wu4.z = GAMMAq * vu.z + wr4.z + (gv * vr.z + (1.0f - gv) * vl.z);
    wu4.w = GAMMAq * vu.w + wr4.w + (gv * vr.w + (1.0f - gv) * vl.w);

    __stcs((float4*)(w_r_out + n), wr4);
    __stcs((float4*)(w_u_out + n), wu4);

    // thread-local top-4 over its 4 values (packed keys; wu > 0)
    unsigned long long tk[4] = {~0ULL, ~0ULL, ~0ULL, ~0ULL};
    const float wvals[4] = {wu4.x, wu4.y, wu4.z, wu4.w};
#pragma unroll
    for (int j = 0; j < 4; j++) {
        const unsigned long long key =
            ((unsigned long long)__float_as_uint(wvals[j]) << 32) | (unsigned int)(n + j);
        if (key < tk[3]) {
            tk[3] = key;
#pragma unroll
            for (int q = 3; q > 0; q--) {
                if (tk[q] < tk[q - 1]) {
                    unsigned long long t = tk[q]; tk[q] = tk[q - 1]; tk[q - 1] = t;
                }
            }
        }
    }

    // per-warp top-4 via 4 rounds of shfl argmin + pop (no barriers)
#pragma unroll
    for (int round = 0; round < 4; round++) {
        unsigned long long v = tk[0];
#pragma unroll
        for (int s = 16; s > 0; s >>= 1) {
            const unsigned long long o = __shfl_xor_sync(0xffffffffu, v, s);
            if (o < v) v = o;
        }
        if (tk[0] == v) {  // unique key -> exactly one popper
            tk[0] = tk[1]; tk[1] = tk[2]; tk[2] = tk[3]; tk[3] = ~0ULL;
        }
        if (lane == 0) sh_keys[warp * 4 + round] = v;
    }
    __syncthreads();

    // warp 0: reduce 128 candidates -> this chunk's top-4 -> g_cand
    if (warp == 0) {
        unsigned long long bk[4] = {~0ULL, ~0ULL, ~0ULL, ~0ULL};
#pragma unroll
        for (int j = 0; j < 4; j++) {
            const unsigned long long key = sh_keys[lane + 32 * j];
            if (key < bk[3]) {
                bk[3] = key;
#pragma unroll
                for (int q = 3; q > 0; q--) {
                    if (bk[q] < bk[q - 1]) {
                        unsigned long long t = bk[q]; bk[q] = bk[q - 1]; bk[q - 1] = t;
                    }
                }
            }
        }
#pragma unroll
        for (int round = 0; round < 4; round++) {
            unsigned long long v = bk[0];
#pragma unroll
            for (int s = 16; s > 0; s >>= 1) {
                const unsigned long long o = __shfl_xor_sync(0xffffffffu, v, s);
                if (o < v) v = o;
            }
            if (bk[0] == v) {
                bk[0] = bk[1]; bk[1] = bk[2]; bk[2] = bk[3]; bk[3] = ~0ULL;
            }
            if (lane == round) g_cand[(b * 4 + c) * 4 + round] = v;
        }
    }
    __syncthreads();

    // ticket: last block of this batch merges + scatters
    if (tid == 0) {
        __threadfence();
        s_last = (atomicAdd(&g_ticket[b], 1) == 3);
    }
    __syncthreads();

    if (s_last && warp == 0) {
        unsigned long long key = (lane < 16) ? g_cand[b * 16 + lane] : ~0ULL;
#pragma unroll
        for (int round = 0; round < 4; round++) {
            unsigned long long v = key;
#pragma unroll
            for (int s = 16; s > 0; s >>= 1) {
                const unsigned long long o = __shfl_xor_sync(0xffffffffu, v, s);
                if (o < v) v = o;
            }
            if (key == v) key = ~0ULL;  // pop winner
            if (lane == round)
                w_lu_out[(int)(unsigned int)(v & 0xffffffffu)] = 1.0f;
        }
    }
}

// ---------------- launch ----------------
extern "C" void kernel_launch(void* const* d_in, const int* in_sizes, int n_in,
                              void* d_out, int out_size) {
    const float* emb    = (const float*)d_in[0];  // (64, 256)
    const float* w_prev = (const float*)d_in[1];  // (64, 3, 16384)
    const float* memory = (const float*)d_in[2];  // (64, 16384, 64)
    const float* W      = (const float*)d_in[3];  // (66, 256)
    const float* bias   = (const float*)d_in[4];  // (66,)
    float* out = (float*)d_out;  // [w (64*3*16384) | new_memory (64*16384*64)]

    const int nwarps = Bq * NOUT;                 // 4224
    const int nblk1 = (nwarps * 32 + 255) / 256;  // 528
    ntm_proj_kernel<<<nblk1, 256>>>(emb, W, bias);

    // K2: PDL secondary of proj
    {
        cudaLaunchConfig_t cfg = {};
        cfg.gridDim = dim3(CHUNKS, Bq);
        cfg.blockDim = dim3(512);
        cudaLaunchAttribute attr[1];
        attr[0].id = cudaLaunchAttributeProgrammaticStreamSerialization;
        attr[0].val.programmaticStreamSerializationAllowed = 1;
        cfg.attrs = attr;
        cfg.numAttrs = 1;
        cudaLaunchKernelEx(&cfg, ntm_stream_kernel, memory, w_prev, out);
    }

    // K3: PDL secondary of K2
    {
        cudaLaunchConfig_t cfg = {};
        cfg.gridDim = dim3(Bq * 4);
        cfg.blockDim = dim3(1024);
        cudaLaunchAttribute attr[1];
        attr[0].id = cudaLaunchAttributeProgrammaticStreamSerialization;
        attr[0].val.programmaticStreamSerializationAllowed = 1;
        cfg.attrs = attr;
        cfg.numAttrs = 1;
        cudaLaunchKernelEx(&cfg, ntm_elem_kernel, w_prev, out);
    }
}